// round 10
// baseline (speedup 1.0000x reference)
#include <cuda_runtime.h>
#include <cstdint>

#define SEQ   512
#define BATCH 512
#define IDIM  300
#define HDIM  300
#define NP    320            // padded hidden for XP layout
#define JH    152            // per-CTA j-half in scan (2*152 = 304 >= 300)
#define MTOT  (SEQ*BATCH)

// GEMM tiling: 64x160 tile, 256 threads, 4m x 10n per thread
#define BM 64
#define BN 160
#define BK 20
#define GTH 256

// scan config: 608 threads = 152 j-singles x 4 k-quarters; 8 batch per thread
#define STHREADS 608
#define KQ       4
#define KCH      (IDIM/KQ)        // 75
#define HB       (304*8)          // one h buffer: [304 j][8 b] floats

// -------- scratch (static device global; no allocations) --------
__device__ float g_XP[(long long)MTOT * NP];     // ~335 MB

// -------- f32x2 helpers (Blackwell packed fp32, PTX-only) --------
__device__ __forceinline__ unsigned long long pack2(float lo, float hi) {
    unsigned long long r;
    asm("mov.b64 %0, {%1, %2};" : "=l"(r) : "f"(lo), "f"(hi));
    return r;
}
__device__ __forceinline__ unsigned long long bcast2(float v) {
    unsigned long long r;
    asm("mov.b64 %0, {%1, %1};" : "=l"(r) : "f"(v));
    return r;
}
__device__ __forceinline__ void ffma2(unsigned long long& d, unsigned long long a, unsigned long long b) {
    asm("fma.rn.f32x2 %0, %1, %2, %3;" : "=l"(d) : "l"(a), "l"(b), "l"(d));
}
__device__ __forceinline__ void fadd2(unsigned long long& d, unsigned long long a) {
    asm("add.rn.f32x2 %0, %1, %2;" : "=l"(d) : "l"(d), "l"(a));
}
__device__ __forceinline__ void unpack2(unsigned long long v, float& lo, float& hi) {
    asm("mov.b64 {%0, %1}, %2;" : "=f"(lo), "=f"(hi) : "l"(v));
}
__device__ __forceinline__ uint32_t smem_u32(const void* p) {
    uint32_t a;
    asm("{ .reg .u64 t; cvta.to.shared.u64 t, %1; cvt.u32.u64 %0, t; }" : "=r"(a) : "l"(p));
    return a;
}
// fast tanh: 1 - 2/(exp(2x)+1); saturates correctly at +-inf
__device__ __forceinline__ float fast_tanh(float x) {
    float e = __expf(2.0f * x);
    return 1.0f - __fdividef(2.0f, e + 1.0f);
}

// -------- x_proj GEMM: XP[m][j] = IN[m][:] . W_ih[j][:] + b_ih[j] + b_hh[j] --------
__global__ __launch_bounds__(GTH, 3) void gemm_xproj(const float* __restrict__ IN,
                                                     const float* __restrict__ Wih,
                                                     const float* __restrict__ bih,
                                                     const float* __restrict__ bhh) {
    __shared__ float As[BK][BM + 4];  // [k][m], padded
    __shared__ float Bs[BK][BN];      // [k][n], n contiguous
    int tid = threadIdx.x;
    int m0 = blockIdx.y * BM;
    int n0 = blockIdx.x * BN;
    int mth = tid >> 4, nth = tid & 15;   // 16 x 16
    int tm0 = mth * 4, tn0 = nth * 10;

    unsigned long long acc[4][5];
    #pragma unroll
    for (int i = 0; i < 4; i++)
        #pragma unroll
        for (int u = 0; u < 5; u++) acc[i][u] = 0ull;

    for (int kk = 0; kk < IDIM; kk += BK) {
        #pragma unroll
        for (int l = 0; l < (BM * BK) / GTH; l++) {
            int idx = tid + l * GTH;
            int m = idx / BK, k = idx % BK;
            As[k][m] = IN[(long long)(m0 + m) * IDIM + kk + k];
        }
        #pragma unroll
        for (int slot = tid; slot < BN * (BK / 4); slot += GTH) {
            int n = slot % BN, kg = slot / BN;
            int gn = n0 + n;
            float4 v = make_float4(0.f, 0.f, 0.f, 0.f);
            if (gn < HDIM)
                v = *(const float4*)&Wih[(long long)gn * IDIM + kk + kg * 4];
            Bs[kg * 4 + 0][n] = v.x;
            Bs[kg * 4 + 1][n] = v.y;
            Bs[kg * 4 + 2][n] = v.z;
            Bs[kg * 4 + 3][n] = v.w;
        }
        __syncthreads();
        #pragma unroll
        for (int k = 0; k < BK; k++) {
            float4 av = *(const float4*)&As[k][tm0];
            const unsigned long long* Bk = (const unsigned long long*)&Bs[k][tn0];
            unsigned long long b0 = Bk[0], b1 = Bk[1], b2 = Bk[2], b3 = Bk[3], b4 = Bk[4];
            unsigned long long a0 = bcast2(av.x), a1 = bcast2(av.y);
            unsigned long long a2 = bcast2(av.z), a3 = bcast2(av.w);
            ffma2(acc[0][0], a0, b0); ffma2(acc[0][1], a0, b1); ffma2(acc[0][2], a0, b2);
            ffma2(acc[0][3], a0, b3); ffma2(acc[0][4], a0, b4);
            ffma2(acc[1][0], a1, b0); ffma2(acc[1][1], a1, b1); ffma2(acc[1][2], a1, b2);
            ffma2(acc[1][3], a1, b3); ffma2(acc[1][4], a1, b4);
            ffma2(acc[2][0], a2, b0); ffma2(acc[2][1], a2, b1); ffma2(acc[2][2], a2, b2);
            ffma2(acc[2][3], a2, b3); ffma2(acc[2][4], a2, b4);
            ffma2(acc[3][0], a3, b0); ffma2(acc[3][1], a3, b1); ffma2(acc[3][2], a3, b2);
            ffma2(acc[3][3], a3, b3); ffma2(acc[3][4], a3, b4);
        }
        __syncthreads();
    }
    float bias[10];
    #pragma unroll
    for (int u = 0; u < 10; u++) {
        int gn = n0 + tn0 + u;
        bias[u] = (gn < HDIM) ? (bih[gn] + bhh[gn]) : 0.f;
    }
    #pragma unroll
    for (int i = 0; i < 4; i++) {
        long long row = (long long)(m0 + tm0 + i) * NP + n0 + tn0;
        #pragma unroll
        for (int u = 0; u < 5; u++) {
            float lo, hi; unpack2(acc[i][u], lo, hi);
            float2 v = make_float2(lo + bias[2 * u], hi + bias[2 * u + 1]);
            *(float2*)&g_XP[row + 2 * u] = v;
        }
    }
}

// -------- recurrent scan: 64 clusters x 2 CTAs, 8 batch per cluster --------
// 608 threads/CTA = (j-single jq 0..151) x (k-quarter kq 0..3); each thread:
// 1 j row x 8 batches x 75 k. W_hh in registers: 75 floats/thread (fits in
// the 107-reg budget at 19 warps -> no spills, 4.75 warps/SMSP latency hiding).
// Inner loop per k: 2x LDS.128 (h, perfect warp-broadcast: all lanes share kq)
// + 1 bcast + 4 FFMA2. Partials ([4 slots][608], conflict-free) reduced by all
// 608 threads (1 u64 output each: j x b-pair), fast_tanh, write h local + peer
// DSMEM. Per-step cluster sync = 1 release-arrive to peer mbarrier + acquire
// try_wait (parity t&1).
__global__ __cluster_dims__(2, 1, 1) __launch_bounds__(STHREADS, 1)
void scan_kernel(const float* __restrict__ Whh, float* __restrict__ out) {
    __shared__ alignas(16) float H[2 * HB];                       // 19456 B
    __shared__ alignas(16) unsigned long long PART[4 * STHREADS]; // 19456 B
    __shared__ unsigned long long mbar;

    int tid = threadIdx.x;
    unsigned rank;
    asm("mov.u32 %0, %%cluster_ctarank;" : "=r"(rank));
    int cid = blockIdx.x >> 1;
    unsigned peer = rank ^ 1u;

    if (tid == 0) {
        asm volatile("mbarrier.init.shared.b64 [%0], 1;"
                     :: "r"(smem_u32(&mbar)) : "memory");
    }
    for (int i = tid; i < 2 * HB; i += STHREADS) H[i] = 0.f;

    // compute-role indices + W_hh row-quarter into registers
    int kq = tid / 152, jq = tid % 152;
    int jglob = rank * JH + jq;
    int kstart = kq * KCH;
    float wa[KCH];
    {
        const float* ra = Whh + (long long)jglob * HDIM + kstart;
        bool va = (jglob < HDIM);
        #pragma unroll
        for (int kk = 0; kk < KCH; kk++) wa[kk] = va ? ra[kk] : 0.f;
    }

    // reduce-role indices: output row jo (local), b-pair bp (0..3)
    int jo = tid % 152, bp = tid / 152;
    int jglob_o = rank * JH + jo;
    int hoff = jglob_o * 8 + bp * 2;                 // within an H buffer (floats)
    uint32_t hbase32 = smem_u32(H);
    uint32_t mbar32 = smem_u32(&mbar);
    const float* xpbase = g_XP + (long long)(cid * 8 + bp * 2) * NP + jglob_o;

    __syncthreads();
    // both CTAs' mbar + H init visible cluster-wide before any arrive/DSMEM
    asm volatile("barrier.cluster.arrive.aligned;" ::: "memory");
    asm volatile("barrier.cluster.wait.aligned;" ::: "memory");

    int p = 0;
    for (int t = 0; t < SEQ; t++) {
        // prefetch xp for this thread's 2 outputs (hidden under MAC loop)
        const float* xr = xpbase + (long long)t * BATCH * NP;
        float x0 = xr[0];
        float x1 = xr[NP];

        // MAC over this thread's k-quarter; W in regs, h broadcast from smem
        unsigned long long A0 = 0, A1 = 0, A2 = 0, A3 = 0;   // b-pairs (0,1)(2,3)(4,5)(6,7)
        const float* hp = H + p * HB + kstart * 8;
        #pragma unroll
        for (int kk = 0; kk < KCH; kk++) {
            ulonglong2 hA = *(const ulonglong2*)(hp + kk * 8);
            ulonglong2 hB = *(const ulonglong2*)(hp + kk * 8 + 4);
            unsigned long long w = bcast2(wa[kk]);
            ffma2(A0, w, hA.x);
            ffma2(A1, w, hA.y);
            ffma2(A2, w, hB.x);
            ffma2(A3, w, hB.y);
        }
        PART[0 * STHREADS + tid] = A0;
        PART[1 * STHREADS + tid] = A1;
        PART[2 * STHREADS + tid] = A2;
        PART[3 * STHREADS + tid] = A3;
        __syncthreads();

        // reduce 4 k-quarters for output (jo, batch pair bp)
        unsigned long long acc = PART[bp * STHREADS + jo];
        #pragma unroll
        for (int q = 1; q < KQ; q++)
            fadd2(acc, PART[bp * STHREADS + q * 152 + jo]);
        float v0, v1;
        unpack2(acc, v0, v1);
        float t0 = fast_tanh(x0 + v0);
        float t1 = fast_tanh(x1 + v1);
        int off = (1 - p) * HB + hoff;
        *(float2*)(H + off) = make_float2(t0, t1);
        uint32_t ra = hbase32 + off * 4;
        asm volatile("{ .reg .b32 pa; .reg .b64 d; mov.b64 d, {%2,%3}; "
                     "mapa.shared::cluster.u32 pa, %0, %1; st.shared::cluster.b64 [pa], d; }"
                     :: "r"(ra), "r"(peer), "f"(t0), "f"(t1) : "memory");

        __syncthreads();   // local H writes + all threads' DSMEM stores ordered
        if (tid == 0) {
            asm volatile("{ .reg .b32 pa; mapa.shared::cluster.u32 pa, %0, %1; "
                         "mbarrier.arrive.release.cluster.shared::cluster.b64 _, [pa]; }"
                         :: "r"(mbar32), "r"(peer) : "memory");
        }
        {
            unsigned ph = (unsigned)(t & 1);
            uint32_t done;
            asm volatile("{ .reg .pred p; "
                         "mbarrier.try_wait.parity.acquire.cluster.shared::cta.b64 p, [%1], %2; "
                         "selp.b32 %0, 1, 0, p; }"
                         : "=r"(done) : "r"(mbar32), "r"(ph) : "memory");
            if (!done) {
                asm volatile("{ .reg .pred P1; "
                             "WL%=: mbarrier.try_wait.parity.acquire.cluster.shared::cta.b64 P1, [%0], %1, 0x989680; "
                             "@P1 bra.uni WD%=; bra.uni WL%=; WD%=: }"
                             :: "r"(mbar32), "r"(ph) : "memory");
            }
        }
        p ^= 1;
    }

    // write final h: each CTA writes its j-half for the cluster's 8 batches
    const float* Hf = H + p * HB;
    int cb0 = cid * 8;
    for (int idx = tid; idx < 8 * JH; idx += STHREADS) {
        int b = idx / JH, jj = idx % JH;
        int j = rank * JH + jj;
        if (j < HDIM) out[(long long)(cb0 + b) * HDIM + j] = Hf[j * 8 + b];
    }
    asm volatile("barrier.cluster.arrive.aligned;" ::: "memory");
    asm volatile("barrier.cluster.wait.aligned;" ::: "memory");
}

extern "C" void kernel_launch(void* const* d_in, const int* in_sizes, int n_in,
                              void* d_out, int out_size) {
    const float* IN  = (const float*)d_in[0];
    const float* Wih = (const float*)d_in[1];
    const float* Whh = (const float*)d_in[2];
    const float* bih = (const float*)d_in[3];
    const float* bhh = (const float*)d_in[4];
    float* out = (float*)d_out;

    dim3 g(NP / BN, MTOT / BM);   // (2, 4096)
    gemm_xproj<<<g, GTH>>>(IN, Wih, bih, bhh);

    scan_kernel<<<128, STHREADS>>>(Whh, out);
}